// round 2
// baseline (speedup 1.0000x reference)
#include <cuda_runtime.h>
#include <cstdint>

// ---------------- problem constants ----------------
#define N_ROWS 16384
#define D_DIM  32

// ---------------- GEMM tiling ----------------
#define TM      128                 // M rows per CTA
#define KB      32                  // K floats per stage (128 B per row)
#define NSTAGE  (N_ROWS / KB)       // 512
#define STAGES  6                   // smem ring buffers
#define PREF    5                   // cp.async groups in flight

#define A_PAD   36                  // padded row stride in floats (bank-conflict free, 16B aligned)
#define A_FLOATS (TM * A_PAD)       // per-stage A floats
#define B_FLOATS (D_DIM * A_PAD)    // per-stage B floats
#define A_BYTES (A_FLOATS * 4)      // 18432
#define B_BYTES (B_FLOATS * 4)      // 4608
#define STAGE_FLOATS (A_FLOATS + B_FLOATS)
#define SMEM_TOTAL (STAGES * (A_BYTES + B_BYTES))   // 138240

// scratch (device globals: no allocation allowed anywhere)
__device__ __align__(256) float g_hT[D_DIM * N_ROWS];   // hT[c][k], tf32-rounded
__device__ __align__(256) float g_h [N_ROWS * D_DIM];   // h[i][c],  fp32

// ---------------- helpers ----------------
__device__ __forceinline__ uint32_t smem_u32(const void* p) {
    uint32_t a;
    asm("{ .reg .u64 t; cvta.to.shared.u64 t, %1; cvt.u32.u64 %0, t; }"
        : "=r"(a) : "l"(p));
    return a;
}

__device__ __forceinline__ void cp16(uint32_t dst, const void* src) {
    asm volatile("cp.async.cg.shared.global [%0], [%1], 16;"
                 :: "r"(dst), "l"(src) : "memory");
}

__device__ __forceinline__ uint32_t f2tf32(float f) {
    uint32_t u;
    asm("cvt.rna.tf32.f32 %0, %1;" : "=r"(u) : "f"(f));
    return u;
}

// m16n8k8 tf32 mma: D += A*B  (row-major A, col-major B, fp32 acc)
__device__ __forceinline__ void mma_tf32(float* c,
                                         uint32_t a0, uint32_t a1, uint32_t a2, uint32_t a3,
                                         uint32_t b0, uint32_t b1) {
    asm volatile(
        "mma.sync.aligned.m16n8k8.row.col.f32.tf32.tf32.f32 "
        "{%0,%1,%2,%3}, {%4,%5,%6,%7}, {%8,%9}, {%0,%1,%2,%3};"
        : "+f"(c[0]), "+f"(c[1]), "+f"(c[2]), "+f"(c[3])
        : "r"(a0), "r"(a1), "r"(a2), "r"(a3), "r"(b0), "r"(b1));
}

// fill one K-stage (A: 128x32 floats, B: 32x32 floats) into ring buffer b
__device__ __forceinline__ void fill_stage(const float* __restrict__ edges,
                                           int m0, int s, int b,
                                           uint32_t sb, int tid) {
    const size_t k0b = (size_t)s * (KB * 4);                  // byte offset along K
    // A tile: rows m0..m0+127, gmem row stride 16384 floats = 65536 B
    const char* baseA = (const char*)edges + (size_t)m0 * 65536 + k0b;
    uint32_t dA = sb + (uint32_t)b * (A_BYTES + B_BYTES);
    #pragma unroll
    for (int it = 0; it < 4; it++) {
        int q = tid + it * 256;               // 1024 chunks of 16B
        int r = q >> 3, c = q & 7;
        uint32_t dst = dA + (uint32_t)(r * (A_PAD * 4) + c * 16);
        cp16(dst, baseA + (size_t)r * 65536 + c * 16);
    }
    // B tile: hT rows 0..31 (same 65536 B row stride)
    const char* baseB = (const char*)g_hT + k0b;
    uint32_t dB = dA + A_BYTES;
    {
        int r = tid >> 3, c = tid & 7;        // 256 chunks of 16B
        uint32_t dst = dB + (uint32_t)(r * (A_PAD * 4) + c * 16);
        cp16(dst, baseB + (size_t)r * 65536 + c * 16);
    }
    asm volatile("cp.async.commit_group;" ::: "memory");
}

// ---------------- kernel 1: h = x @ w1^T ----------------
__global__ void __launch_bounds__(256) h_kernel(const float* __restrict__ x,
                                                const float* __restrict__ w1) {
    __shared__ float sw[D_DIM * D_DIM];
    __shared__ float sx[8 * D_DIM];
    int tid = threadIdx.x;
    for (int i = tid; i < D_DIM * D_DIM; i += 256) sw[i] = w1[i];
    int row0 = blockIdx.x * 8;
    for (int i = tid; i < 8 * D_DIM; i += 256) sx[i] = x[row0 * D_DIM + i];
    __syncthreads();
    int r = tid >> 5, c = tid & 31;
    float acc = 0.f;
    #pragma unroll
    for (int d = 0; d < D_DIM; d++) acc += sx[r * D_DIM + d] * sw[c * D_DIM + d];
    int i = row0 + r;
    g_h[i * D_DIM + c] = acc;                              // fp32 self term
    g_hT[c * N_ROWS + i] = __uint_as_float(f2tf32(acc));   // tf32-rounded B operand
}

// ---------------- kernel 2: out = edges @ h + h ----------------
__global__ void __launch_bounds__(256, 1)
gcn_gemm_kernel(const float* __restrict__ edges, float* __restrict__ out) {
    extern __shared__ float smem[];
    uint32_t sb = smem_u32(smem);
    const int tid = threadIdx.x, wid = tid >> 5, lane = tid & 31;
    const int g = lane >> 2, t = lane & 3;          // fragment group / thread-in-group
    const int m0 = blockIdx.x * TM;

    float acc[4][4];                                 // 4 n-tiles x 4 regs
    #pragma unroll
    for (int nt = 0; nt < 4; nt++)
        #pragma unroll
        for (int r = 0; r < 4; r++) acc[nt][r] = 0.f;

    // prologue: fill stages 0..PREF-1
    for (int s = 0; s < PREF; s++) fill_stage(edges, m0, s, s, sb, tid);

    // per-thread fragment base offsets (floats)
    const int aBase = (wid * 16 + g) * A_PAD + t;    // a0; a1=+8*A_PAD; a2=+4; a3=+8*A_PAD+4

    for (int s = 0; s < NSTAGE; s++) {
        asm volatile("cp.async.wait_group %0;" :: "n"(PREF - 1) : "memory");
        __syncthreads();

        // prefetch stage s+PREF into buffer (s+PREF)%STAGES  (== computed at s-1, safe)
        int sp = s + PREF;
        if (sp < NSTAGE) fill_stage(edges, m0, sp, sp % STAGES, sb, tid);
        else asm volatile("cp.async.commit_group;" ::: "memory");

        const float* stA = smem + (s % STAGES) * STAGE_FLOATS;
        const float* stB = stA + A_FLOATS;

        #pragma unroll
        for (int kk = 0; kk < 4; kk++) {
            const int ko = kk * 8;
            uint32_t a0 = f2tf32(stA[aBase + ko]);
            uint32_t a1 = f2tf32(stA[aBase + 8 * A_PAD + ko]);
            uint32_t a2 = f2tf32(stA[aBase + 4 + ko]);
            uint32_t a3 = f2tf32(stA[aBase + 8 * A_PAD + 4 + ko]);
            #pragma unroll
            for (int nt = 0; nt < 4; nt++) {
                const int bBase = (nt * 8 + g) * A_PAD + t + ko;
                uint32_t b0 = __float_as_uint(stB[bBase]);       // pre-rounded tf32
                uint32_t b1 = __float_as_uint(stB[bBase + 4]);
                mma_tf32(acc[nt], a0, a1, a2, a3, b0, b1);
            }
        }
    }

    // epilogue: out = acc + h   (fragment D mapping: rows g,g+8; cols 2t,2t+1)
    const int row0 = m0 + wid * 16 + g;
    #pragma unroll
    for (int half = 0; half < 2; half++) {
        int row = row0 + half * 8;
        const float2* hr = (const float2*)(g_h + row * D_DIM);
        float2* o = (float2*)(out + (size_t)row * D_DIM);
        #pragma unroll
        for (int nt = 0; nt < 4; nt++) {
            int c2 = (nt * 8 + t * 2) >> 1;          // float2 index within row
            float2 hv = hr[c2];
            float2 v;
            v.x = acc[nt][half * 2 + 0] + hv.x;
            v.y = acc[nt][half * 2 + 1] + hv.y;
            o[c2] = v;
        }
    }
}

// ---------------- launch ----------------
extern "C" void kernel_launch(void* const* d_in, const int* in_sizes, int n_in,
                              void* d_out, int out_size) {
    const float* x     = (const float*)d_in[0];
    const float* edges = (const float*)d_in[1];
    const float* w1    = (const float*)d_in[2];
    float* out = (float*)d_out;

    cudaFuncSetAttribute(gcn_gemm_kernel,
                         cudaFuncAttributeMaxDynamicSharedMemorySize, SMEM_TOTAL);

    h_kernel<<<N_ROWS / 8, 256>>>(x, w1);
    gcn_gemm_kernel<<<N_ROWS / TM, 256, SMEM_TOTAL>>>(edges, out);
}